// round 16
// baseline (speedup 1.0000x reference)
#include <cuda_runtime.h>
#include <math.h>

#define KLEN   4096
#define NFREQ  2049      // K/2 + 1
#define NH     1025      // folded freqs h=0..1024 (f=h pairs with f=2048-h)
#define NSIG   12
#define NBATCH 64
#define NLAG   51        // 2*25 + 1
#define NTAU   26        // tau = 0..25
#define NTP    13        // tau pairs (even, odd)
#define NPAIR  78        // 12*13/2 unique (n<=m) pairs
#define NS     9         // frequency slices (144 CTAs)
#define CH     114       // folded freqs per slice (9*114 = 1026 >= 1025)
#define CHH    57        // half-slice per thread (2 halves combine in-CTA)
#define CHP    115       // padded smem stride (conflict-free float4 su loads)
#define BPG    4         // batches per gcc CTA
#define GCC_BLOCK 640    // 8 groups x 80 threads = 4 batches x 2 freq-halves
#define OUTB   (NSIG*NSIG*NLAG)   // 7344 floats per batch

// -------- device scratch (static: no allocations allowed) --------
__device__ float2 g_dft2[36 * 64];                // (c,s) of 2*pi*j*a/64, rows j=0..35
__device__ float4 g_dftp[36 * 32];                // [j][p]: (c_2p, c_2p+1, s_2p, s_2p+1)
__device__ float4 g_tw1[33 * 64];                 // [d][b]: (c, s, tmr, tms) stage-1 twiddle
__device__ float4 g_lagp[NH * NTP];               // (wcE, wcO, wsE, wsO) at [h*13+tp]
__device__ float2 g_spec[NBATCH * NSIG * NFREQ];  // PHAT-normalized spectra
__device__ unsigned long long g_part2[NS][NBATCH][NPAIR][NTAU];  // packed (g+, g-)

// -------- packed fp32x2 helpers --------
__device__ __forceinline__ unsigned long long fma_x2(unsigned long long a,
                                                     unsigned long long b,
                                                     unsigned long long c) {
    unsigned long long d;
    asm("fma.rn.f32x2 %0, %1, %2, %3;" : "=l"(d) : "l"(a), "l"(b), "l"(c));
    return d;
}
__device__ __forceinline__ unsigned long long pack2(float lo, float hi) {
    unsigned long long d;
    asm("mov.b64 %0, {%1, %2};" : "=l"(d) : "f"(lo), "f"(hi));
    return d;
}
__device__ __forceinline__ void unpack2(unsigned long long v, float& lo, float& hi) {
    asm("mov.b64 {%0, %1}, %2;" : "=f"(lo), "=f"(hi) : "l"(v));
}

// ================= init: twiddle tables =================
__global__ void init_tables_kernel() {
    int t = blockIdx.x * blockDim.x + threadIdx.x;
    int stride = gridDim.x * blockDim.x;
    for (int i = t; i < 36 * 64; i += stride) {
        int j = i >> 6, a = i & 63;
        float s, c;
        sincospif((float)(j * a) * (1.0f / 32.0f), &s, &c);   // 2*pi*j*a/64
        g_dft2[i] = make_float2(c, s);
    }
    for (int i = t; i < 36 * 32; i += stride) {
        int j = i >> 5, p = i & 31;
        float s0, c0, s1, c1;
        sincospif((float)(j * (2 * p)) * (1.0f / 32.0f), &s0, &c0);
        sincospif((float)(j * (2 * p + 1)) * (1.0f / 32.0f), &s1, &c1);
        g_dftp[i] = make_float4(c0, c1, s0, s1);
    }
    for (int i = t; i < 33 * 64; i += stride) {
        int d = i >> 6, b = i & 63;
        float s, c, es, ec;
        sincospif((float)(b * d) * (1.0f / 2048.0f), &s, &c);   // W4096^{bd} = c - i s
        sincospif((float)b * (1.0f / 32.0f), &es, &ec);          // 2*pi*b/64
        float tmr = ec * c + es * s;     // cos(2pi b/64 - th)
        float tms = es * c - ec * s;     // sin(2pi b/64 - th)
        g_tw1[i] = make_float4(c, s, tmr, tms);
    }
    for (int i = t; i < NH * NTP; i += stride) {
        int h = i / NTP, tp = i - h * NTP;
        int tau0 = 2 * tp, tau1 = tau0 + 1;
        float s0, c0, s1, c1;
        sincospif((float)(h * tau0) * (1.0f / 2048.0f), &s0, &c0);
        sincospif((float)(h * tau1) * (1.0f / 2048.0f), &s1, &c1);
        float w = ((h == 0) ? 1.0f : 2.0f) * (1.0f / (float)KLEN);
        g_lagp[i] = make_float4(w * c0, w * c1, w * s0, w * s1);
    }
}

// ---- stage-2 j-pass: NJ packed accumulator quads over all 16 b-pairs ----
template<int J0, int NJ>
__device__ __forceinline__ void stage2_pass(const float2* __restrict__ Yt,
                                            const float4* __restrict__ T2,
                                            int d, int q0, float2 z32,
                                            float2* __restrict__ outp) {
    unsigned long long aR[NJ], aI[NJ], aY[NJ], aX[NJ];
    #pragma unroll
    for (int jj = 0; jj < NJ; jj++) { aR[jj] = 0ull; aI[jj] = 0ull; aY[jj] = 0ull; aX[jj] = 0ull; }

    for (int p = 0; p < 16; p++) {
        int b = 2 * p;
        float2 z1a = Yt[b * 66 + d];
        float2 z2a = Yt[(64 - b) * 66 + d];      // b=0 -> row 64 (zeroed)
        float2 z1b = Yt[(b + 1) * 66 + d];
        float2 z2b = Yt[(63 - b) * 66 + d];
        unsigned long long peR = pack2(z1a.x + z2a.x, z1b.x + z2b.x);  // (zex, zex')
        unsigned long long peI = pack2(z1a.y + z2a.y, z1b.y + z2b.y);  // (zey, zey')
        unsigned long long poY = pack2(z1a.y - z2a.y, z1b.y - z2b.y);  // (zoy, zoy')
        unsigned long long poX = pack2(z1a.x - z2a.x, z1b.x - z2b.x);  // (zox, zox')
        #pragma unroll
        for (int jj = 0; jj < NJ; jj++) {
            int cc = q0 + 4 * (J0 + jj);         // <=35; padded rows, junk discarded
            longlong2 w = *(const longlong2*)(T2 + cc * 32 + p); // (c,c'),(s,s') bcast
            aR[jj] = fma_x2(peR, (unsigned long long)w.x, aR[jj]);
            aI[jj] = fma_x2(peI, (unsigned long long)w.x, aI[jj]);
            aY[jj] = fma_x2(poY, (unsigned long long)w.y, aY[jj]);
            aX[jj] = fma_x2(poX, (unsigned long long)w.y, aX[jj]);
        }
    }

    #pragma unroll
    for (int jj = 0; jj < NJ; jj++) {
        int cc = q0 + 4 * (J0 + jj);
        int f = cc * 64 + d;
        if (cc <= 32 && f <= 2048) {
            float rl, rh, il, ih, yl, yh, xl, xh;
            unpack2(aR[jj], rl, rh);
            unpack2(aI[jj], il, ih);
            unpack2(aY[jj], yl, yh);
            unpack2(aX[jj], xl, xh);
            float sg = (cc & 1) ? -1.f : 1.f;
            float Xr = (rl + rh) + (yl + yh) + sg * z32.x;
            float Xi = (il + ih) - (xl + xh) + sg * z32.y;
            float u = fmaf(Xr, Xr, fmaf(Xi, Xi, 1e-30f));
            float inv = rsqrtf(u);
            outp[f] = make_float2(Xr * inv, Xi * inv);
        }
    }
}

// ================= FFT (64x64 four-step, fully folded) + PHAT ========================
// Stage 1 = R12-exact. Stage 2: b-pair lane packing (4 fma_x2 per b-pair per cc,
// was 8 FFMA) via a same-size (c,c',s,s') pair table. Yt ALIASES the dead xf region
// (x03 read pre-sync) => smem 71.2 KB, 3 CTAs/SM and 2 waves preserved.
__global__ __launch_bounds__(256, 3) void fft_phat_kernel(const float* __restrict__ x) {
    extern __shared__ float smem[];
    float2* T1 = (float2*)smem;                     // [36][64] (c,s)
    float4* T2 = (float4*)(T1 + 36 * 64);           // [36][32] (c,c',s,s')
    float2* xf = (float2*)(T2 + 36 * 32);           // [32][64]: (xe,-xo); a=0 -> (x0,x32)
    float2* Yt = xf;                                // alias after sync2: [65][66]

    const int t = threadIdx.x;
    const float* xin = x + (size_t)blockIdx.x * KLEN;

    for (int i = t; i < 36 * 64; i += 256) T1[i] = g_dft2[i];
    for (int i = t; i < 36 * 32; i += 256) T2[i] = g_dftp[i];
    for (int i = t; i < 32 * 64; i += 256) {
        int a = i >> 6, b = i & 63;
        if (a == 0) {
            xf[b] = make_float2(xin[b], xin[32 * 64 + b]);
        } else {
            float v1 = xin[a * 64 + b];
            float v2 = xin[(64 - a) * 64 + b];
            xf[a * 64 + b] = make_float2(v1 + v2, v2 - v1);   // (xe, -xo)
        }
    }
    __syncthreads();                               // sync1: xf + tables ready

    const int bb = t & 63, q0 = t >> 6;

    // ---- stage 1 mainloop: 9 packed accumulators (yr, yi) for d = q0 + 4i ----
    unsigned long long acc[9];
    #pragma unroll
    for (int i = 0; i < 9; i++) acc[i] = 0ull;
    {
        unsigned long long vp = *(const unsigned long long*)(xf + 64 + bb);
        #pragma unroll
        for (int i = 0; i < 9; i++) {
            int d = q0 + 4 * i;
            unsigned long long cs = *(const unsigned long long*)(T1 + d * 64 + 1);
            acc[i] = fma_x2(vp, cs, acc[i]);
        }
    }
    for (int a = 2; a < 32; a += 2) {
        unsigned long long vp0 = *(const unsigned long long*)(xf + a * 64 + bb);
        unsigned long long vp1 = *(const unsigned long long*)(xf + (a + 1) * 64 + bb);
        #pragma unroll
        for (int i = 0; i < 9; i++) {
            int d = q0 + 4 * i;                    // d<=35; padded rows, junk discarded
            longlong2 w = *(const longlong2*)(T1 + d * 64 + a);
            acc[i] = fma_x2(vp0, (unsigned long long)w.x, acc[i]);
            acc[i] = fma_x2(vp1, (unsigned long long)w.y, acc[i]);
        }
    }
    float2 x03 = xf[bb];                           // (x0, x32) — read BEFORE sync2
    __syncthreads();                               // sync2: all xf reads complete

    // zero Yt row 64 (pseudo-mirror for b=0) — region now owned by Yt
    for (int i = t; i < 66; i += 256) Yt[64 * 66 + i] = make_float2(0.f, 0.f);

    // ---- stage 1 epilogue: twiddle + Hermitian mirror into Yt ----
    #pragma unroll
    for (int i = 0; i < 9; i++) {
        int d = q0 + 4 * i;
        if (d <= 32) {
            float yr, yi;
            unpack2(acc[i], yr, yi);
            yr += x03.x + ((d & 1) ? -x03.y : x03.y);
            float4 w = g_tw1[d * 64 + bb];          // (c, s, tmr, tms)
            Yt[bb * 66 + d] = make_float2(yr * w.x + yi * w.y, yi * w.x - yr * w.y);
            if (d >= 1 && d <= 31) {
                Yt[bb * 66 + (64 - d)] =
                    make_float2(yr * w.z - yi * w.w, -(yr * w.w + yi * w.z));
            }
        }
    }
    __syncthreads();                               // sync3: Yt ready

    // ---- stage 2: two j-passes (5 + 4 accumulator quads, regs <= 84) ----
    {
        const int d = bb;
        float2 z32 = Yt[32 * 66 + d];
        float2* outp = g_spec + (size_t)blockIdx.x * NFREQ;
        stage2_pass<0, 5>(Yt, T2, d, q0, z32, outp);
        stage2_pass<5, 4>(Yt, T2, d, q0, z32, outp);
    }
}

// ================= GCC: folded cross-spectrum x lag twiddles (frozen R12 form) =======
__global__ __launch_bounds__(GCC_BLOCK, 1) void gcc_kernel() {
    extern __shared__ float smem[];
    float4* su = (float4*)smem;                  // [BPG][12][CHP] (Ar,Ai,Br,Bi)
    float4* T  = su + BPG * NSIG * CHP;          // [CH][13] (wcE,wcO,wsE,wsO)
    unsigned long long* stage = (unsigned long long*)su;  // reused after mainloop

    const int t = threadIdx.x;
    const int bg = blockIdx.x;
    const int f0 = blockIdx.y * CH;

    for (int i = t; i < BPG * NSIG * CH; i += GCC_BLOCK) {
        int g = i / (NSIG * CH);
        int r = i - g * (NSIG * CH);
        int sig = r / CH, hl = r - sig * CH;
        int f = f0 + hl;
        const float2* sp = g_spec + ((size_t)(bg * BPG + g) * NSIG + sig) * NFREQ;
        float2 A = (f <= 1024) ? sp[f] : make_float2(0.f, 0.f);
        float2 B = (f <= 1023) ? sp[2048 - f] : make_float2(0.f, 0.f);
        su[(g * NSIG + sig) * CHP + hl] = make_float4(A.x, A.y, B.x, B.y);
    }
    for (int i = t; i < CH * NTP; i += GCC_BLOCK) {
        int hl = i / NTP;
        int f = f0 + hl;
        T[i] = (f <= 1024) ? g_lagp[f * NTP + (i - hl * NTP)]
                           : make_float4(0.f, 0.f, 0.f, 0.f);
    }
    __syncthreads();

    const int grp = t / 80, u = t - grp * 80;
    const int gb = grp >> 1;          // batch within CTA (0..3)
    const int half = grp & 1;         // frequency half
    const bool active = (u < NPAIR);

    unsigned long long accU[NTP], accV[NTP];   // lanes = (even tau, odd tau)
    #pragma unroll
    for (int i = 0; i < NTP; i++) { accU[i] = 0ull; accV[i] = 0ull; }

    if (active) {
        int n = 0, rem = u;
        #pragma unroll
        for (int k = 0; k < NSIG; k++) {
            int cnt = NSIG - k;
            if (rem < cnt) { n = k; break; }
            rem -= cnt;
        }
        const int m = n + rem;

        const float4* pn = su + gb * (NSIG * CHP) + n * CHP;
        const float4* pm = su + gb * (NSIG * CHP) + m * CHP;

        const int h0 = half * CHH;
        for (int hl = h0; hl < h0 + CHH; hl++) {
            float4 an = pn[hl];
            float4 am = pm[hl];
            float U1 = an.x * am.x + an.y * am.y;
            float V1 = an.y * am.x - an.x * am.y;
            float U2 = an.z * am.z + an.w * am.w;
            float V2 = an.w * am.z - an.z * am.w;
            unsigned long long pU = pack2(U1 + U2, U1 - U2);   // (Ue, Uo)
            unsigned long long pV = pack2(V1 - V2, V1 + V2);   // (Vme, Vpo)
            const longlong2* tw = (const longlong2*)(T + (size_t)hl * NTP);
            #pragma unroll
            for (int tp = 0; tp < NTP; tp++) {
                longlong2 w = tw[tp];   // .x = (wcE,wcO), .y = (wsE,wsO)
                accU[tp] = fma_x2((unsigned long long)w.x, pU, accU[tp]);
                accV[tp] = fma_x2((unsigned long long)w.y, pV, accV[tp]);
            }
        }
    }
    __syncthreads();   // su reads complete; staging region now safe to overwrite

    if (active && half == 1) {
        unsigned long long* st = stage + ((size_t)gb * NPAIR + u) * 26;
        #pragma unroll
        for (int tp = 0; tp < NTP; tp++) { st[tp] = accU[tp]; st[NTP + tp] = accV[tp]; }
    }
    __syncthreads();

    if (active && half == 0) {
        const unsigned long long* st = stage + ((size_t)gb * NPAIR + u) * 26;
        const unsigned long long ONE2 = pack2(1.0f, 1.0f);
        #pragma unroll
        for (int tp = 0; tp < NTP; tp++) {
            accU[tp] = fma_x2(ONE2, st[tp], accU[tp]);
            accV[tp] = fma_x2(ONE2, st[NTP + tp], accV[tp]);
        }
        unsigned long long* pr = &g_part2[blockIdx.y][bg * BPG + gb][u][0];
        #pragma unroll
        for (int tp = 0; tp < NTP; tp++) {
            float aE, aO, bE, bO;
            unpack2(accU[tp], aE, aO);
            unpack2(accV[tp], bE, bO);
            pr[2 * tp]     = pack2(aE - bE, aE + bE);   // (g+, g-) even tau
            pr[2 * tp + 1] = pack2(aO - bO, aO + bO);   // (g+, g-) odd tau
        }
    }
}

// ================= reduce partials + triangular mirror expansion (frozen R8) =========
__global__ void reduce_kernel(float* __restrict__ out) {
    int i = blockIdx.x * blockDim.x + threadIdx.x;
    if (i >= NBATCH * NPAIR * 13) return;
    int b = i / (NPAIR * 13);
    int r = i - b * (NPAIR * 13);
    int p = r / 13, k2 = r - p * 13;
    int tau0 = 2 * k2, tau1 = tau0 + 1;

    float gp0 = 0.f, gm0 = 0.f, gp1 = 0.f, gm1 = 0.f;
    #pragma unroll
    for (int s = 0; s < NS; s++) {
        ulonglong2 v = *(const ulonglong2*)&g_part2[s][b][p][tau0];
        float lo, hi;
        unpack2(v.x, lo, hi); gp0 += lo; gm0 += hi;
        unpack2(v.y, lo, hi); gp1 += lo; gm1 += hi;
    }

    int n = 0, rem = p;
    #pragma unroll
    for (int k = 0; k < NSIG; k++) {
        int cnt = NSIG - k;
        if (rem < cnt) { n = k; break; }
        rem -= cnt;
    }
    int m = n + rem;

    float* ob  = out + (size_t)b * OUTB;
    float* onm = ob + (n * NSIG + m) * NLAG;
    onm[tau0] = gp0;
    onm[tau1] = gp1;
    if (tau0 > 0) onm[NLAG - tau0] = gm0;
    onm[NLAG - tau1] = gm1;
    if (n != m) {
        float* omn = ob + (m * NSIG + n) * NLAG;
        omn[tau0] = gm0;
        omn[tau1] = gm1;
        if (tau0 > 0) omn[NLAG - tau0] = gp0;
        omn[NLAG - tau1] = gp1;
    }
}

// ================= launch =================
extern "C" void kernel_launch(void* const* d_in, const int* in_sizes, int n_in,
                              void* d_out, int out_size) {
    const float* x = (const float*)d_in[0];
    float* out = (float*)d_out;

    const int fft_smem = 36 * 64 * (int)sizeof(float2)      // T1      18,432
                       + 36 * 32 * (int)sizeof(float4)      // T2      18,432
                       + 65 * 66 * (int)sizeof(float2);     // region  34,320 => 71,184
    const int gcc_smem = BPG * NSIG * CHP * (int)sizeof(float4)
                       + CH * NTP * (int)sizeof(float4);    // 112,032 B

    cudaFuncSetAttribute(fft_phat_kernel, cudaFuncAttributeMaxDynamicSharedMemorySize, fft_smem);
    cudaFuncSetAttribute(gcc_kernel,      cudaFuncAttributeMaxDynamicSharedMemorySize, gcc_smem);

    init_tables_kernel<<<296, 128>>>();
    fft_phat_kernel<<<NBATCH * NSIG, 256, fft_smem>>>(x);
    gcc_kernel<<<dim3(NBATCH / BPG, NS), GCC_BLOCK, gcc_smem>>>();
    const int rthreads = NBATCH * NPAIR * 13;
    reduce_kernel<<<(rthreads + 255) / 256, 256>>>(out);
}